// round 4
// baseline (speedup 1.0000x reference)
#include <cuda_runtime.h>
#include <math.h>
#include <stdint.h>

#define DINL __device__ __forceinline__

// ---------- packed fp32x2 helpers (sm_103a) ----------
DINL unsigned long long pack2(float x, float y){
    unsigned long long r;
    asm("mov.b64 %0, {%1,%2};" : "=l"(r) : "f"(x), "f"(y));
    return r;
}
DINL void unpack2(unsigned long long v, float& x, float& y){
    asm("mov.b64 {%0,%1}, %2;" : "=f"(x), "=f"(y) : "l"(v));
}
DINL void fma2(unsigned long long& d, unsigned long long a, unsigned long long b){
    asm("fma.rn.f32x2 %0, %1, %2, %0;" : "+l"(d) : "l"(a), "l"(b));
}
DINL float sigm(float x){ return 1.0f / (1.0f + expf(-x)); }

// ---------- sizes ----------
#define B_   8
#define S_   32
#define P_   5
#define C_   528
#define H_   784
#define M_   128
#define NSP  196
#define TOT  1280
#define BSN  256
#define OUTW 1697

// ---------- device scratch ----------
__device__ __align__(16) float g_GI[BSN * 3 * H_];
__device__ __align__(16) float g_h[2][B_ * H_];
__device__ __align__(16) float g_pref[BSN * H_];
__device__ __align__(16) float g_patt[BSN * M_];
__device__ __align__(16) float g_mot[BSN * M_];
__device__ __align__(16) float g_Wt[C_ * M_];
__device__ __align__(16) float g_vidpre[(size_t)TOT * 784];
__device__ __align__(16) float g_bnPart[TOT * 8];
__device__ __align__(16) float g_mstats[2 * M_];
__device__ __align__(16) float g_vstats[8];

// ---------- prep: transpose Wv_w [128,528] -> g_Wt [528,128]; zero h0 ----------
__global__ void k_prep(const float* __restrict__ Wv_w){
    int i = blockIdx.x * 256 + threadIdx.x;
    if (i < C_ * M_){
        int m = i / C_, c = i % C_;
        g_Wt[c * M_ + m] = Wv_w[i];
    }
    if (i < B_ * H_) g_h[0][i] = 0.0f;
}

// ---------- generic NT GEMM: C[i,j] = sum_k A[i,k]*B[j,k] (+bias[j]) ----------
__global__ void k_gemm_nt(const float* __restrict__ Aext, const float* __restrict__ Bm,
                          const float* __restrict__ bias, int atag, int ctag,
                          int M, int N, int K){
    const float* A = (atag == 0) ? Aext : g_pref;
    float* C = (ctag == 0) ? g_GI : (ctag == 1 ? g_patt : g_mot);
    __shared__ float As[32][33];
    __shared__ float Bs[64][33];
    int i0 = blockIdx.y * 32, j0 = blockIdx.x * 64;
    int tid = threadIdx.x;
    int ti = tid >> 4, tj = tid & 15;
    float acc[2][4] = {{0,0,0,0},{0,0,0,0}};
    for (int k0 = 0; k0 < K; k0 += 32){
        #pragma unroll
        for (int r = 0; r < 4; r++){
            int idx = tid + r * 256, row = idx >> 5, col = idx & 31;
            float v = 0.0f;
            if (i0 + row < M && k0 + col < K) v = A[(size_t)(i0 + row) * K + k0 + col];
            As[row][col] = v;
        }
        #pragma unroll
        for (int r = 0; r < 8; r++){
            int idx = tid + r * 256, row = idx >> 5, col = idx & 31;
            float v = 0.0f;
            if (j0 + row < N && k0 + col < K) v = Bm[(size_t)(j0 + row) * K + k0 + col];
            Bs[row][col] = v;
        }
        __syncthreads();
        #pragma unroll
        for (int kk = 0; kk < 32; kk++){
            float a0 = As[ti*2][kk], a1 = As[ti*2+1][kk];
            float b0 = Bs[tj*4][kk], b1 = Bs[tj*4+1][kk];
            float b2 = Bs[tj*4+2][kk], b3 = Bs[tj*4+3][kk];
            acc[0][0] += a0*b0; acc[0][1] += a0*b1; acc[0][2] += a0*b2; acc[0][3] += a0*b3;
            acc[1][0] += a1*b0; acc[1][1] += a1*b1; acc[1][2] += a1*b2; acc[1][3] += a1*b3;
        }
        __syncthreads();
    }
    #pragma unroll
    for (int r = 0; r < 2; r++)
        #pragma unroll
        for (int c = 0; c < 4; c++){
            int i = i0 + ti*2 + r, j = j0 + tj*4 + c;
            if (i < M && j < N){
                float v = acc[r][c];
                if (bias) v += bias[j];
                C[(size_t)i * N + j] = v;
            }
        }
}

// ---------- GRU recurrent step v3 ----------
// grid(196), block(128) = 4 warps. Warp = ONE hidden unit j, ALL 3 gates,
// all 8 batches. Weights streamed as float4 (21 LDG.128 in flight per warp,
// fully unrolled) -> ~14 KB/SM outstanding, covers L2 latency at 42 B/cyc/SM.
// Accumulate in packed f32x2. Gate recombination is warp-local.
#define GRU_THREADS 128
__global__ void __launch_bounds__(GRU_THREADS)
k_gru_step(const float* __restrict__ Whh, const float* __restrict__ bhh, int s){
    __shared__ __align__(16) float4 hs4[B_][H_ / 4];   // [8][196]
    const float* hin = g_h[s & 1];
    float* hout = g_h[(s + 1) & 1];
    int tid = threadIdx.x, wid = tid >> 5, lane = tid & 31;

    // cooperative load of h into smem (1568 float4)
    {
        const float4* src = reinterpret_cast<const float4*>(hin);
        float4* dst = &hs4[0][0];
        for (int i = tid; i < B_ * (H_ / 4); i += GRU_THREADS) dst[i] = src[i];
    }
    __syncthreads();

    int j = blockIdx.x * 4 + wid;

    unsigned long long acc[3][B_];
    #pragma unroll
    for (int g = 0; g < 3; g++)
        #pragma unroll
        for (int b = 0; b < B_; b++) acc[g][b] = 0ULL;

    if (s > 0){
        const float4* w0 = reinterpret_cast<const float4*>(Whh + (size_t)j * H_);
        const float4* w1 = reinterpret_cast<const float4*>(Whh + (size_t)(H_ + j) * H_);
        const float4* w2 = reinterpret_cast<const float4*>(Whh + (size_t)(2 * H_ + j) * H_);
        #pragma unroll
        for (int it = 0; it < 7; it++){
            int k4 = lane + it * 32;
            if (it < 6 || lane < 4){
                float4 a0 = w0[k4];
                float4 a1 = w1[k4];
                float4 a2 = w2[k4];
                unsigned long long p0l = pack2(a0.x, a0.y), p0h = pack2(a0.z, a0.w);
                unsigned long long p1l = pack2(a1.x, a1.y), p1h = pack2(a1.z, a1.w);
                unsigned long long p2l = pack2(a2.x, a2.y), p2h = pack2(a2.z, a2.w);
                #pragma unroll
                for (int b = 0; b < B_; b++){
                    float4 h4 = hs4[b][k4];
                    unsigned long long hl = pack2(h4.x, h4.y), hh = pack2(h4.z, h4.w);
                    fma2(acc[0][b], p0l, hl); fma2(acc[0][b], p0h, hh);
                    fma2(acc[1][b], p1l, hl); fma2(acc[1][b], p1h, hh);
                    fma2(acc[2][b], p2l, hl); fma2(acc[2][b], p2h, hh);
                }
            }
        }
    }

    // horizontal + cross-lane reduce
    float red[3][B_];
    #pragma unroll
    for (int g = 0; g < 3; g++)
        #pragma unroll
        for (int b = 0; b < B_; b++){
            float x, y; unpack2(acc[g][b], x, y);
            red[g][b] = x + y;
        }
    #pragma unroll
    for (int o = 16; o; o >>= 1)
        #pragma unroll
        for (int g = 0; g < 3; g++)
            #pragma unroll
            for (int b = 0; b < B_; b++)
                red[g][b] += __shfl_down_sync(0xffffffffu, red[g][b], o);

    if (lane == 0){
        const float* hsf = reinterpret_cast<const float*>(&hs4[0][0]);
        float br = bhh[j], bz = bhh[H_ + j], bn = bhh[2 * H_ + j];
        #pragma unroll
        for (int b = 0; b < B_; b++){
            int bs = b * S_ + s;
            const float* gi = g_GI + (size_t)bs * (3 * H_);
            float r = sigm(gi[j] + red[0][b] + br);
            float z = sigm(gi[H_ + j] + red[1][b] + bz);
            float n = tanhf(gi[2 * H_ + j] + r * (red[2][b] + bn));
            float hn = (1.0f - z) * n + z * hsf[b * H_ + j];
            hout[b * H_ + j] = hn;
            g_pref[(size_t)bs * H_ + j] = hn;
        }
    }
}

// ---------- fused attention + softmax + 1x1 conv; one CTA per t ----------
#define ATT_THREADS 448
#define NCC 8
__global__ void __launch_bounds__(ATT_THREADS, 1)
k_att(const float* __restrict__ video, const float* __restrict__ Wv_b,
      const float* __restrict__ Wpv, const float* __restrict__ conv_w,
      const float* __restrict__ conv_b){
    __shared__ float Vs[2][NCC * NSP];
    __shared__ __align__(16) float Ws[2][NCC * M_];
    __shared__ float sc[NSP];
    __shared__ float attb[NSP];
    __shared__ float cw[4 * C_];
    __shared__ float wS[14][8];

    int t = blockIdx.x;
    const float* V = video + (size_t)t * (C_ * NSP);
    int tid = threadIdx.x;
    int tj = tid & 15, ti = tid >> 4;
    int m0 = tj * 8, n0 = ti * 7;

    for (int i = tid; i < 4 * C_; i += ATT_THREADS) cw[i] = conv_w[i];

    int wst[3];
    #pragma unroll
    for (int r = 0; r < 3; r++){
        int idx = tid + r * ATT_THREADS;
        if (idx < NCC * M_){
            int cc = idx >> 7, m = idx & 127;
            int p = m >> 1;
            int q = ((p & 3) << 4) | (p >> 2);
            wst[r] = cc * M_ + q * 2 + (m & 1);
        } else wst[r] = -1;
    }

    #pragma unroll
    for (int r = 0; r < 4; r++){
        int idx = tid + r * ATT_THREADS;
        if (idx < NCC * NSP) Vs[0][idx] = V[idx];
    }
    #pragma unroll
    for (int r = 0; r < 3; r++)
        if (wst[r] >= 0) Ws[0][wst[r]] = g_Wt[tid + r * ATT_THREADS];
    __syncthreads();

    unsigned long long acc[7][4];
    #pragma unroll
    for (int i = 0; i < 7; i++)
        #pragma unroll
        for (int j = 0; j < 4; j++) acc[i][j] = 0ULL;

    const int NSTAGE = C_ / NCC; // 66
    for (int st = 0; st < NSTAGE; st++){
        int cur = st & 1;
        float vtmp[4], wtmp[3];
        bool has = (st + 1 < NSTAGE);
        if (has){
            const float* Vn = V + (st + 1) * (NCC * NSP);
            const float* Wn = g_Wt + (st + 1) * (NCC * M_);
            #pragma unroll
            for (int r = 0; r < 4; r++){
                int idx = tid + r * ATT_THREADS;
                vtmp[r] = (idx < NCC * NSP) ? Vn[idx] : 0.0f;
            }
            #pragma unroll
            for (int r = 0; r < 3; r++)
                wtmp[r] = (wst[r] >= 0) ? Wn[tid + r * ATT_THREADS] : 0.0f;
        }
        const float* vsc = Vs[cur];
        const unsigned long long* wsc = reinterpret_cast<const unsigned long long*>(Ws[cur]);
        #pragma unroll
        for (int cc = 0; cc < NCC; cc++){
            unsigned long long bv[4];
            #pragma unroll
            for (int j = 0; j < 4; j++) bv[j] = wsc[cc * 64 + j * 16 + tj];
            #pragma unroll
            for (int i = 0; i < 7; i++){
                float a = vsc[cc * NSP + n0 + i];
                unsigned long long av = pack2(a, a);
                #pragma unroll
                for (int j = 0; j < 4; j++) fma2(acc[i][j], av, bv[j]);
            }
        }
        if (has){
            float* vd = Vs[cur ^ 1];
            float* wd = Ws[cur ^ 1];
            #pragma unroll
            for (int r = 0; r < 4; r++){
                int idx = tid + r * ATT_THREADS;
                if (idx < NCC * NSP) vd[idx] = vtmp[r];
            }
            #pragma unroll
            for (int r = 0; r < 3; r++)
                if (wst[r] >= 0) wd[wst[r]] = wtmp[r];
        }
        __syncthreads();
    }

    int bs = t / P_;
    const float* pa = g_patt + (size_t)bs * M_;
    float sp[7] = {0,0,0,0,0,0,0};
    #pragma unroll
    for (int j = 0; j < 4; j++){
        int m = m0 + 2 * j;
        float2 pv = *reinterpret_cast<const float2*>(pa + m);
        float2 bb = *reinterpret_cast<const float2*>(Wv_b + m);
        float2 ww = *reinterpret_cast<const float2*>(Wpv + m);
        #pragma unroll
        for (int i = 0; i < 7; i++){
            float x, y; unpack2(acc[i][j], x, y);
            x = tanhf(x + pv.x + bb.x);
            y = tanhf(y + pv.y + bb.y);
            sp[i] += x * ww.x + y * ww.y;
        }
    }
    #pragma unroll
    for (int o = 8; o >= 1; o >>= 1)
        #pragma unroll
        for (int i = 0; i < 7; i++)
            sp[i] += __shfl_xor_sync(0xffffffffu, sp[i], o);
    if (tj == 0){
        #pragma unroll
        for (int i = 0; i < 7; i++) sc[n0 + i] = sp[i];
    }
    __syncthreads();

    if (tid < 32){
        float mx = -3.4e38f;
        for (int n = tid; n < NSP; n += 32) mx = fmaxf(mx, sc[n]);
        #pragma unroll
        for (int o = 16; o; o >>= 1) mx = fmaxf(mx, __shfl_xor_sync(0xffffffffu, mx, o));
        float sm = 0.0f;
        for (int n = tid; n < NSP; n += 32){ float e = expf(sc[n] - mx); attb[n] = e; sm += e; }
        #pragma unroll
        for (int o = 16; o; o >>= 1) sm += __shfl_xor_sync(0xffffffffu, sm, o);
        float inv = 1.0f / sm;
        for (int n = tid; n < NSP; n += 32) attb[n] *= inv;
    }
    __syncthreads();

    float d0 = 0.f, d1 = 0.f, d2 = 0.f, d3 = 0.f;
    int n = tid >> 1, half = tid & 1;
    if (tid < 392){
        const float4* fp = reinterpret_cast<const float4*>(V + (size_t)n * C_ + half * 264);
        #pragma unroll 4
        for (int q = 0; q < 66; q++){
            float4 v4 = fp[q];
            int c = half * 264 + q * 4;
            d0 += v4.x*cw[c]       + v4.y*cw[c+1]       + v4.z*cw[c+2]       + v4.w*cw[c+3];
            d1 += v4.x*cw[528+c]   + v4.y*cw[528+c+1]   + v4.z*cw[528+c+2]   + v4.w*cw[528+c+3];
            d2 += v4.x*cw[1056+c]  + v4.y*cw[1056+c+1]  + v4.z*cw[1056+c+2]  + v4.w*cw[1056+c+3];
            d3 += v4.x*cw[1584+c]  + v4.y*cw[1584+c+1]  + v4.z*cw[1584+c+2]  + v4.w*cw[1584+c+3];
        }
    }
    d0 += __shfl_xor_sync(0xffffffffu, d0, 1);
    d1 += __shfl_xor_sync(0xffffffffu, d1, 1);
    d2 += __shfl_xor_sync(0xffffffffu, d2, 1);
    d3 += __shfl_xor_sync(0xffffffffu, d3, 1);

    float dsum[4] = {0,0,0,0}, dsq[4] = {0,0,0,0};
    if (tid < 392 && half == 0){
        float an = attb[n];
        float vv[4];
        vv[0] = an * d0 + conv_b[0];
        vv[1] = an * d1 + conv_b[1];
        vv[2] = an * d2 + conv_b[2];
        vv[3] = an * d3 + conv_b[3];
        #pragma unroll
        for (int o = 0; o < 4; o++){
            g_vidpre[(size_t)t * 784 + o * NSP + n] = vv[o];
            dsum[o] = vv[o];
            dsq[o] = vv[o] * vv[o];
        }
    }
    #pragma unroll
    for (int o = 0; o < 4; o++){
        #pragma unroll
        for (int sh = 16; sh; sh >>= 1){
            dsum[o] += __shfl_down_sync(0xffffffffu, dsum[o], sh);
            dsq[o]  += __shfl_down_sync(0xffffffffu, dsq[o], sh);
        }
    }
    int wid = tid >> 5, lane = tid & 31;
    if (lane == 0){
        #pragma unroll
        for (int o = 0; o < 4; o++){ wS[wid][o] = dsum[o]; wS[wid][4 + o] = dsq[o]; }
    }
    __syncthreads();
    if (tid < 8){
        float a = 0.f;
        #pragma unroll
        for (int w = 0; w < 14; w++) a += wS[w][tid];
        g_bnPart[t * 8 + tid] = a;
    }
}

// ---------- motion BN stats over 256 rows ----------
__global__ void k_mstats(){
    int m = threadIdx.x;
    float sum = 0.f, sq = 0.f;
    for (int r = 0; r < BSN; r++){
        float v = g_mot[r * M_ + m];
        sum += v; sq += v * v;
    }
    float mu = sum / (float)BSN;
    float var = sq / (float)BSN - mu * mu;
    g_mstats[m] = mu;
    g_mstats[M_ + m] = rsqrtf(var + 1e-5f);
}

// ---------- video BN stats reduce ----------
__global__ void k_vstats(){
    __shared__ float red[256];
    __shared__ float tot[8];
    int tid = threadIdx.x;
    float part[8] = {0,0,0,0,0,0,0,0};
    for (int t = tid; t < TOT; t += 256)
        #pragma unroll
        for (int k = 0; k < 8; k++) part[k] += g_bnPart[t * 8 + k];
    for (int k = 0; k < 8; k++){
        red[tid] = part[k];
        __syncthreads();
        for (int o = 128; o; o >>= 1){
            if (tid < o) red[tid] += red[tid + o];
            __syncthreads();
        }
        if (tid == 0) tot[k] = red[0];
        __syncthreads();
    }
    if (tid < 4){
        float cnt = (float)TOT * (float)NSP;
        float mu = tot[tid] / cnt;
        float var = tot[4 + tid] / cnt - mu * mu;
        g_vstats[tid] = mu;
        g_vstats[4 + tid] = rsqrtf(var + 1e-5f);
    }
}

// ---------- final assembly ----------
__global__ void k_final(const float* __restrict__ tw,
                        const float* __restrict__ vbn_g, const float* __restrict__ vbn_b,
                        const float* __restrict__ mbn_g, const float* __restrict__ mbn_b,
                        float* __restrict__ out){
    int t = blockIdx.x, bs = t / P_, p = t % P_;
    float* o = out + (size_t)t * OUTW;
    for (int c = threadIdx.x; c < OUTW; c += 256){
        float v;
        if (c == 0) v = tw[p];
        else if (c < 785) v = g_pref[(size_t)bs * H_ + (c - 1)];
        else if (c < 913){
            int m = c - 785;
            float x = g_mot[bs * M_ + m];
            v = fmaxf((x - g_mstats[m]) * g_mstats[M_ + m] * mbn_g[m] + mbn_b[m], 0.f);
        } else {
            int idx = c - 913, ch = idx / NSP;
            float x = g_vidpre[(size_t)t * 784 + idx];
            v = fmaxf((x - g_vstats[ch]) * g_vstats[4 + ch] * vbn_g[ch] + vbn_b[ch], 0.f);
        }
        o[c] = v;
    }
}

// ---------- launcher ----------
extern "C" void kernel_launch(void* const* d_in, const int* in_sizes, int n_in,
                              void* d_out, int out_size){
    const float* fov      = (const float*)d_in[0];
    const float* motion   = (const float*)d_in[1];
    const float* video    = (const float*)d_in[2];
    const float* timew    = (const float*)d_in[3];
    const float* gru_w_ih = (const float*)d_in[4];
    const float* gru_w_hh = (const float*)d_in[5];
    const float* gru_b_ih = (const float*)d_in[6];
    const float* gru_b_hh = (const float*)d_in[7];
    const float* Wp       = (const float*)d_in[8];
    const float* Wv_w     = (const float*)d_in[9];
    const float* Wv_b     = (const float*)d_in[10];
    const float* Wpv_w    = (const float*)d_in[11];
    const float* conv_w   = (const float*)d_in[13];
    const float* conv_b   = (const float*)d_in[14];
    const float* vbn_g    = (const float*)d_in[15];
    const float* vbn_b    = (const float*)d_in[16];
    const float* me_w     = (const float*)d_in[17];
    const float* me_b     = (const float*)d_in[18];
    const float* mbn_g    = (const float*)d_in[19];
    const float* mbn_b    = (const float*)d_in[20];
    float* out = (float*)d_out;

    k_prep<<<264, 256>>>(Wv_w);
    k_gemm_nt<<<dim3(37, 8), 256>>>(fov, gru_w_ih, gru_b_ih, 0, 0, BSN, 3 * H_, C_);
    for (int s = 0; s < S_; s++)
        k_gru_step<<<196, GRU_THREADS>>>(gru_w_hh, gru_b_hh, s);
    k_gemm_nt<<<dim3(2, 8), 256>>>(nullptr, Wp, nullptr, 1, 1, BSN, M_, H_);
    k_gemm_nt<<<dim3(2, 8), 256>>>(motion, me_w, me_b, 0, 2, BSN, M_, 90);
    k_att<<<TOT, ATT_THREADS>>>(video, Wv_b, Wpv_w, conv_w, conv_b);
    k_mstats<<<1, 128>>>();
    k_vstats<<<1, 256>>>();
    k_final<<<TOT, 256>>>(timew, vbn_g, vbn_b, mbn_g, mbn_b, out);
}

// round 5
// speedup vs baseline: 1.0261x; 1.0261x over previous
#include <cuda_runtime.h>
#include <math.h>
#include <stdint.h>

#define DINL __device__ __forceinline__

// ---------- packed fp32x2 helpers (sm_103a) ----------
DINL unsigned long long pack2(float x, float y){
    unsigned long long r;
    asm("mov.b64 %0, {%1,%2};" : "=l"(r) : "f"(x), "f"(y));
    return r;
}
DINL void unpack2(unsigned long long v, float& x, float& y){
    asm("mov.b64 {%0,%1}, %2;" : "=f"(x), "=f"(y) : "l"(v));
}
DINL void fma2(unsigned long long& d, unsigned long long a, unsigned long long b){
    asm("fma.rn.f32x2 %0, %1, %2, %0;" : "+l"(d) : "l"(a), "l"(b));
}
DINL float sigm(float x){ return 1.0f / (1.0f + expf(-x)); }

// ---------- sizes ----------
#define B_   8
#define S_   32
#define P_   5
#define C_   528
#define H_   784
#define M_   128
#define NSP  196
#define TOT  1280
#define BSN  256
#define OUTW 1697

// GRU persistent kernel config
#define GRU_NCTA 131
#define GRU_JPC  6
#define GRU_THREADS 192
#define GRU_SMEM_FLOATS (GRU_JPC * 3 * H_ + B_ * H_)   // 14112 + 6272 = 20384
#define GRU_SMEM_BYTES  (GRU_SMEM_FLOATS * 4)          // 81536

// ---------- device scratch ----------
__device__ __align__(16) float g_GI[BSN * 3 * H_];
__device__ __align__(16) float g_h[2][B_ * H_];
__device__ __align__(16) float g_pref[BSN * H_];
__device__ __align__(16) float g_patt[BSN * M_];
__device__ __align__(16) float g_mot[BSN * M_];
__device__ __align__(16) float g_Wt[C_ * M_];
__device__ __align__(16) float g_vidpre[(size_t)TOT * 784];
__device__ __align__(16) float g_bnPart[TOT * 8];
__device__ __align__(16) float g_mstats[2 * M_];
__device__ __align__(16) float g_vstats[8];
__device__ unsigned g_bar;

// ---------- prep: transpose Wv_w [128,528] -> g_Wt [528,128]; reset barrier ----------
__global__ void k_prep(const float* __restrict__ Wv_w){
    int i = blockIdx.x * 256 + threadIdx.x;
    if (i < C_ * M_){
        int m = i / C_, c = i % C_;
        g_Wt[c * M_ + m] = Wv_w[i];
    }
    if (i == 0) g_bar = 0u;
}

// ---------- generic NT GEMM: C[i,j] = sum_k A[i,k]*B[j,k] (+bias[j]) ----------
__global__ void k_gemm_nt(const float* __restrict__ Aext, const float* __restrict__ Bm,
                          const float* __restrict__ bias, int atag, int ctag,
                          int M, int N, int K){
    const float* A = (atag == 0) ? Aext : g_pref;
    float* C = (ctag == 0) ? g_GI : (ctag == 1 ? g_patt : g_mot);
    __shared__ float As[32][33];
    __shared__ float Bs[64][33];
    int i0 = blockIdx.y * 32, j0 = blockIdx.x * 64;
    int tid = threadIdx.x;
    int ti = tid >> 4, tj = tid & 15;
    float acc[2][4] = {{0,0,0,0},{0,0,0,0}};
    for (int k0 = 0; k0 < K; k0 += 32){
        #pragma unroll
        for (int r = 0; r < 4; r++){
            int idx = tid + r * 256, row = idx >> 5, col = idx & 31;
            float v = 0.0f;
            if (i0 + row < M && k0 + col < K) v = A[(size_t)(i0 + row) * K + k0 + col];
            As[row][col] = v;
        }
        #pragma unroll
        for (int r = 0; r < 8; r++){
            int idx = tid + r * 256, row = idx >> 5, col = idx & 31;
            float v = 0.0f;
            if (j0 + row < N && k0 + col < K) v = Bm[(size_t)(j0 + row) * K + k0 + col];
            Bs[row][col] = v;
        }
        __syncthreads();
        #pragma unroll
        for (int kk = 0; kk < 32; kk++){
            float a0 = As[ti*2][kk], a1 = As[ti*2+1][kk];
            float b0 = Bs[tj*4][kk], b1 = Bs[tj*4+1][kk];
            float b2 = Bs[tj*4+2][kk], b3 = Bs[tj*4+3][kk];
            acc[0][0] += a0*b0; acc[0][1] += a0*b1; acc[0][2] += a0*b2; acc[0][3] += a0*b3;
            acc[1][0] += a1*b0; acc[1][1] += a1*b1; acc[1][2] += a1*b2; acc[1][3] += a1*b3;
        }
        __syncthreads();
    }
    #pragma unroll
    for (int r = 0; r < 2; r++)
        #pragma unroll
        for (int c = 0; c < 4; c++){
            int i = i0 + ti*2 + r, j = j0 + tj*4 + c;
            if (i < M && j < N){
                float v = acc[r][c];
                if (bias) v += bias[j];
                C[(size_t)i * N + j] = v;
            }
        }
}

// ---------- persistent GRU: all 32 steps in one launch ----------
// grid(131), block(192) = 6 warps; warp = one hidden unit j (all 3 gates, 8 batches).
// Whh slice (6 j x 3 gates x 784) resident in smem for the whole sequence.
// h exchanged via g_h ping-pong + cumulative-counter grid barrier (all CTAs resident).
__global__ void __launch_bounds__(GRU_THREADS)
k_gru_all(const float* __restrict__ Whh, const float* __restrict__ bhh){
    extern __shared__ float dyn[];
    float* wsm = dyn;                                   // [6*3][784]
    float4* hs4 = reinterpret_cast<float4*>(dyn + GRU_JPC * 3 * H_); // [8][196]
    const float* hsf = dyn + GRU_JPC * 3 * H_;

    int tid = threadIdx.x, wid = tid >> 5, lane = tid & 31;
    int jbase = blockIdx.x * GRU_JPC;
    int j = jbase + wid;
    bool active = (j < H_);

    // load weight slice once (rows: jj*3+g)
    for (int idx = tid; idx < GRU_JPC * 3 * H_; idx += GRU_THREADS){
        int row = idx / H_, k = idx - row * H_;
        int jj = row / 3, g = row - jj * 3;
        int jr = jbase + jj;
        wsm[idx] = (jr < H_) ? Whh[(size_t)(g * H_ + jr) * H_ + k] : 0.0f;
    }

    float br = 0.f, bz = 0.f, bn = 0.f;
    if (active && lane == 0){
        br = bhh[j]; bz = bhh[H_ + j]; bn = bhh[2 * H_ + j];
    }
    const float4* w0 = reinterpret_cast<const float4*>(wsm + (wid * 3 + 0) * H_);
    const float4* w1 = reinterpret_cast<const float4*>(wsm + (wid * 3 + 1) * H_);
    const float4* w2 = reinterpret_cast<const float4*>(wsm + (wid * 3 + 2) * H_);

    __syncthreads();

    for (int s = 0; s < S_; s++){
        // stage h(s) into smem (h(0) = 0, skip)
        if (s > 0){
            const float4* src = reinterpret_cast<const float4*>(g_h[s & 1]);
            for (int i = tid; i < B_ * (H_ / 4); i += GRU_THREADS) hs4[i] = src[i];
        }
        __syncthreads();

        float red[3][B_];
        #pragma unroll
        for (int g = 0; g < 3; g++)
            #pragma unroll
            for (int b = 0; b < B_; b++) red[g][b] = 0.0f;

        if (active && s > 0){
            unsigned long long acc[3][B_];
            #pragma unroll
            for (int g = 0; g < 3; g++)
                #pragma unroll
                for (int b = 0; b < B_; b++) acc[g][b] = 0ULL;

            #pragma unroll
            for (int it = 0; it < 7; it++){
                int k4 = lane + it * 32;
                if (it < 6 || lane < 4){
                    float4 a0 = w0[k4];
                    float4 a1 = w1[k4];
                    float4 a2 = w2[k4];
                    unsigned long long p0l = pack2(a0.x, a0.y), p0h = pack2(a0.z, a0.w);
                    unsigned long long p1l = pack2(a1.x, a1.y), p1h = pack2(a1.z, a1.w);
                    unsigned long long p2l = pack2(a2.x, a2.y), p2h = pack2(a2.z, a2.w);
                    #pragma unroll
                    for (int b = 0; b < B_; b++){
                        float4 h4 = hs4[b * (H_ / 4) + k4];
                        unsigned long long hl = pack2(h4.x, h4.y), hh = pack2(h4.z, h4.w);
                        fma2(acc[0][b], p0l, hl); fma2(acc[0][b], p0h, hh);
                        fma2(acc[1][b], p1l, hl); fma2(acc[1][b], p1h, hh);
                        fma2(acc[2][b], p2l, hl); fma2(acc[2][b], p2h, hh);
                    }
                }
            }
            #pragma unroll
            for (int g = 0; g < 3; g++)
                #pragma unroll
                for (int b = 0; b < B_; b++){
                    float x, y; unpack2(acc[g][b], x, y);
                    red[g][b] = x + y;
                }
            #pragma unroll
            for (int o = 16; o; o >>= 1)
                #pragma unroll
                for (int g = 0; g < 3; g++)
                    #pragma unroll
                    for (int b = 0; b < B_; b++)
                        red[g][b] += __shfl_down_sync(0xffffffffu, red[g][b], o);
        }

        if (active && lane == 0){
            float* hout = g_h[(s + 1) & 1];
            #pragma unroll
            for (int b = 0; b < B_; b++){
                int bs = b * S_ + s;
                const float* gi = g_GI + (size_t)bs * (3 * H_);
                float r = sigm(gi[j] + red[0][b] + br);
                float z = sigm(gi[H_ + j] + red[1][b] + bz);
                float n = tanhf(gi[2 * H_ + j] + r * (red[2][b] + bn));
                float hold = (s > 0) ? hsf[b * H_ + j] : 0.0f;
                float hn = (1.0f - z) * n + z * hold;
                hout[b * H_ + j] = hn;
                g_pref[(size_t)bs * H_ + j] = hn;
            }
        }

        // grid barrier (cumulative counter; all 131 CTAs resident)
        __threadfence();
        __syncthreads();
        if (tid == 0){
            atomicAdd(&g_bar, 1u);
            unsigned target = (unsigned)GRU_NCTA * (unsigned)(s + 1);
            while (*((volatile unsigned*)&g_bar) < target) { }
        }
        __syncthreads();
        __threadfence();
    }
}

// ---------- fused attention + softmax + 1x1 conv; one CTA per t ----------
#define ATT_THREADS 448
#define NCC 8
__global__ void __launch_bounds__(ATT_THREADS, 1)
k_att(const float* __restrict__ video, const float* __restrict__ Wv_b,
      const float* __restrict__ Wpv, const float* __restrict__ conv_w,
      const float* __restrict__ conv_b){
    __shared__ float Vs[2][NCC * NSP];
    __shared__ __align__(16) float Ws[2][NCC * M_];
    __shared__ float sc[NSP];
    __shared__ float attb[NSP];
    __shared__ float cw[4 * C_];
    __shared__ float wS[14][8];

    int t = blockIdx.x;
    const float* V = video + (size_t)t * (C_ * NSP);
    int tid = threadIdx.x;
    int tj = tid & 15, ti = tid >> 4;
    int m0 = tj * 8, n0 = ti * 7;

    for (int i = tid; i < 4 * C_; i += ATT_THREADS) cw[i] = conv_w[i];

    int wst[3];
    #pragma unroll
    for (int r = 0; r < 3; r++){
        int idx = tid + r * ATT_THREADS;
        if (idx < NCC * M_){
            int cc = idx >> 7, m = idx & 127;
            int p = m >> 1;
            int q = ((p & 3) << 4) | (p >> 2);
            wst[r] = cc * M_ + q * 2 + (m & 1);
        } else wst[r] = -1;
    }

    #pragma unroll
    for (int r = 0; r < 4; r++){
        int idx = tid + r * ATT_THREADS;
        if (idx < NCC * NSP) Vs[0][idx] = V[idx];
    }
    #pragma unroll
    for (int r = 0; r < 3; r++)
        if (wst[r] >= 0) Ws[0][wst[r]] = g_Wt[tid + r * ATT_THREADS];
    __syncthreads();

    unsigned long long acc[7][4];
    #pragma unroll
    for (int i = 0; i < 7; i++)
        #pragma unroll
        for (int j = 0; j < 4; j++) acc[i][j] = 0ULL;

    const int NSTAGE = C_ / NCC; // 66
    for (int st = 0; st < NSTAGE; st++){
        int cur = st & 1;
        float vtmp[4], wtmp[3];
        bool has = (st + 1 < NSTAGE);
        if (has){
            const float* Vn = V + (st + 1) * (NCC * NSP);
            const float* Wn = g_Wt + (st + 1) * (NCC * M_);
            #pragma unroll
            for (int r = 0; r < 4; r++){
                int idx = tid + r * ATT_THREADS;
                vtmp[r] = (idx < NCC * NSP) ? Vn[idx] : 0.0f;
            }
            #pragma unroll
            for (int r = 0; r < 3; r++)
                wtmp[r] = (wst[r] >= 0) ? Wn[tid + r * ATT_THREADS] : 0.0f;
        }
        const float* vsc = Vs[cur];
        const unsigned long long* wsc = reinterpret_cast<const unsigned long long*>(Ws[cur]);
        #pragma unroll
        for (int cc = 0; cc < NCC; cc++){
            unsigned long long bv[4];
            #pragma unroll
            for (int j = 0; j < 4; j++) bv[j] = wsc[cc * 64 + j * 16 + tj];
            #pragma unroll
            for (int i = 0; i < 7; i++){
                float a = vsc[cc * NSP + n0 + i];
                unsigned long long av = pack2(a, a);
                #pragma unroll
                for (int j = 0; j < 4; j++) fma2(acc[i][j], av, bv[j]);
            }
        }
        if (has){
            float* vd = Vs[cur ^ 1];
            float* wd = Ws[cur ^ 1];
            #pragma unroll
            for (int r = 0; r < 4; r++){
                int idx = tid + r * ATT_THREADS;
                if (idx < NCC * NSP) vd[idx] = vtmp[r];
            }
            #pragma unroll
            for (int r = 0; r < 3; r++)
                if (wst[r] >= 0) wd[wst[r]] = wtmp[r];
        }
        __syncthreads();
    }

    int bs = t / P_;
    const float* pa = g_patt + (size_t)bs * M_;
    float sp[7] = {0,0,0,0,0,0,0};
    #pragma unroll
    for (int j = 0; j < 4; j++){
        int m = m0 + 2 * j;
        float2 pv = *reinterpret_cast<const float2*>(pa + m);
        float2 bb = *reinterpret_cast<const float2*>(Wv_b + m);
        float2 ww = *reinterpret_cast<const float2*>(Wpv + m);
        #pragma unroll
        for (int i = 0; i < 7; i++){
            float x, y; unpack2(acc[i][j], x, y);
            x = tanhf(x + pv.x + bb.x);
            y = tanhf(y + pv.y + bb.y);
            sp[i] += x * ww.x + y * ww.y;
        }
    }
    #pragma unroll
    for (int o = 8; o >= 1; o >>= 1)
        #pragma unroll
        for (int i = 0; i < 7; i++)
            sp[i] += __shfl_xor_sync(0xffffffffu, sp[i], o);
    if (tj == 0){
        #pragma unroll
        for (int i = 0; i < 7; i++) sc[n0 + i] = sp[i];
    }
    __syncthreads();

    if (tid < 32){
        float mx = -3.4e38f;
        for (int n = tid; n < NSP; n += 32) mx = fmaxf(mx, sc[n]);
        #pragma unroll
        for (int o = 16; o; o >>= 1) mx = fmaxf(mx, __shfl_xor_sync(0xffffffffu, mx, o));
        float sm = 0.0f;
        for (int n = tid; n < NSP; n += 32){ float e = expf(sc[n] - mx); attb[n] = e; sm += e; }
        #pragma unroll
        for (int o = 16; o; o >>= 1) sm += __shfl_xor_sync(0xffffffffu, sm, o);
        float inv = 1.0f / sm;
        for (int n = tid; n < NSP; n += 32) attb[n] *= inv;
    }
    __syncthreads();

    float d0 = 0.f, d1 = 0.f, d2 = 0.f, d3 = 0.f;
    int n = tid >> 1, half = tid & 1;
    if (tid < 392){
        const float4* fp = reinterpret_cast<const float4*>(V + (size_t)n * C_ + half * 264);
        #pragma unroll 4
        for (int q = 0; q < 66; q++){
            float4 v4 = fp[q];
            int c = half * 264 + q * 4;
            d0 += v4.x*cw[c]       + v4.y*cw[c+1]       + v4.z*cw[c+2]       + v4.w*cw[c+3];
            d1 += v4.x*cw[528+c]   + v4.y*cw[528+c+1]   + v4.z*cw[528+c+2]   + v4.w*cw[528+c+3];
            d2 += v4.x*cw[1056+c]  + v4.y*cw[1056+c+1]  + v4.z*cw[1056+c+2]  + v4.w*cw[1056+c+3];
            d3 += v4.x*cw[1584+c]  + v4.y*cw[1584+c+1]  + v4.z*cw[1584+c+2]  + v4.w*cw[1584+c+3];
        }
    }
    d0 += __shfl_xor_sync(0xffffffffu, d0, 1);
    d1 += __shfl_xor_sync(0xffffffffu, d1, 1);
    d2 += __shfl_xor_sync(0xffffffffu, d2, 1);
    d3 += __shfl_xor_sync(0xffffffffu, d3, 1);

    float dsum[4] = {0,0,0,0}, dsq[4] = {0,0,0,0};
    if (tid < 392 && half == 0){
        float an = attb[n];
        float vv[4];
        vv[0] = an * d0 + conv_b[0];
        vv[1] = an * d1 + conv_b[1];
        vv[2] = an * d2 + conv_b[2];
        vv[3] = an * d3 + conv_b[3];
        #pragma unroll
        for (int o = 0; o < 4; o++){
            g_vidpre[(size_t)t * 784 + o * NSP + n] = vv[o];
            dsum[o] = vv[o];
            dsq[o] = vv[o] * vv[o];
        }
    }
    #pragma unroll
    for (int o = 0; o < 4; o++){
        #pragma unroll
        for (int sh = 16; sh; sh >>= 1){
            dsum[o] += __shfl_down_sync(0xffffffffu, dsum[o], sh);
            dsq[o]  += __shfl_down_sync(0xffffffffu, dsq[o], sh);
        }
    }
    int wid = tid >> 5, lane = tid & 31;
    if (lane == 0){
        #pragma unroll
        for (int o = 0; o < 4; o++){ wS[wid][o] = dsum[o]; wS[wid][4 + o] = dsq[o]; }
    }
    __syncthreads();
    if (tid < 8){
        float a = 0.f;
        #pragma unroll
        for (int w = 0; w < 14; w++) a += wS[w][tid];
        g_bnPart[t * 8 + tid] = a;
    }
}

// ---------- motion BN stats over 256 rows ----------
__global__ void k_mstats(){
    int m = threadIdx.x;
    float sum = 0.f, sq = 0.f;
    for (int r = 0; r < BSN; r++){
        float v = g_mot[r * M_ + m];
        sum += v; sq += v * v;
    }
    float mu = sum / (float)BSN;
    float var = sq / (float)BSN - mu * mu;
    g_mstats[m] = mu;
    g_mstats[M_ + m] = rsqrtf(var + 1e-5f);
}

// ---------- video BN stats reduce ----------
__global__ void k_vstats(){
    __shared__ float red[256];
    __shared__ float tot[8];
    int tid = threadIdx.x;
    float part[8] = {0,0,0,0,0,0,0,0};
    for (int t = tid; t < TOT; t += 256)
        #pragma unroll
        for (int k = 0; k < 8; k++) part[k] += g_bnPart[t * 8 + k];
    for (int k = 0; k < 8; k++){
        red[tid] = part[k];
        __syncthreads();
        for (int o = 128; o; o >>= 1){
            if (tid < o) red[tid] += red[tid + o];
            __syncthreads();
        }
        if (tid == 0) tot[k] = red[0];
        __syncthreads();
    }
    if (tid < 4){
        float cnt = (float)TOT * (float)NSP;
        float mu = tot[tid] / cnt;
        float var = tot[4 + tid] / cnt - mu * mu;
        g_vstats[tid] = mu;
        g_vstats[4 + tid] = rsqrtf(var + 1e-5f);
    }
}

// ---------- final assembly ----------
__global__ void k_final(const float* __restrict__ tw,
                        const float* __restrict__ vbn_g, const float* __restrict__ vbn_b,
                        const float* __restrict__ mbn_g, const float* __restrict__ mbn_b,
                        float* __restrict__ out){
    int t = blockIdx.x, bs = t / P_, p = t % P_;
    float* o = out + (size_t)t * OUTW;
    for (int c = threadIdx.x; c < OUTW; c += 256){
        float v;
        if (c == 0) v = tw[p];
        else if (c < 785) v = g_pref[(size_t)bs * H_ + (c - 1)];
        else if (c < 913){
            int m = c - 785;
            float x = g_mot[bs * M_ + m];
            v = fmaxf((x - g_mstats[m]) * g_mstats[M_ + m] * mbn_g[m] + mbn_b[m], 0.f);
        } else {
            int idx = c - 913, ch = idx / NSP;
            float x = g_vidpre[(size_t)t * 784 + idx];
            v = fmaxf((x - g_vstats[ch]) * g_vstats[4 + ch] * vbn_g[ch] + vbn_b[ch], 0.f);
        }
        o[c] = v;
    }
}

// ---------- launcher ----------
extern "C" void kernel_launch(void* const* d_in, const int* in_sizes, int n_in,
                              void* d_out, int out_size){
    const float* fov      = (const float*)d_in[0];
    const float* motion   = (const float*)d_in[1];
    const float* video    = (const float*)d_in[2];
    const float* timew    = (const float*)d_in[3];
    const float* gru_w_ih = (const float*)d_in[4];
    const float* gru_w_hh = (const float*)d_in[5];
    const float* gru_b_ih = (const float*)d_in[6];
    const float* gru_b_hh = (const float*)d_in[7];
    const float* Wp       = (const float*)d_in[8];
    const float* Wv_w     = (const float*)d_in[9];
    const float* Wv_b     = (const float*)d_in[10];
    const float* Wpv_w    = (const float*)d_in[11];
    const float* conv_w   = (const float*)d_in[13];
    const float* conv_b   = (const float*)d_in[14];
    const float* vbn_g    = (const float*)d_in[15];
    const float* vbn_b    = (const float*)d_in[16];
    const float* me_w     = (const float*)d_in[17];
    const float* me_b     = (const float*)d_in[18];
    const float* mbn_g    = (const float*)d_in[19];
    const float* mbn_b    = (const float*)d_in[20];
    float* out = (float*)d_out;

    static bool attr_done = false;
    if (!attr_done){
        cudaFuncSetAttribute(k_gru_all, cudaFuncAttributeMaxDynamicSharedMemorySize,
                             GRU_SMEM_BYTES);
        attr_done = true;
    }

    k_prep<<<264, 256>>>(Wv_w);
    k_gemm_nt<<<dim3(37, 8), 256>>>(fov, gru_w_ih, gru_b_ih, 0, 0, BSN, 3 * H_, C_);
    k_gru_all<<<GRU_NCTA, GRU_THREADS, GRU_SMEM_BYTES>>>(gru_w_hh, gru_b_hh);
    k_gemm_nt<<<dim3(2, 8), 256>>>(nullptr, Wp, nullptr, 1, 1, BSN, M_, H_);
    k_gemm_nt<<<dim3(2, 8), 256>>>(motion, me_w, me_b, 0, 2, BSN, M_, 90);
    k_att<<<TOT, ATT_THREADS>>>(video, Wv_b, Wpv_w, conv_w, conv_b);
    k_mstats<<<1, 128>>>();
    k_vstats<<<1, 256>>>();
    k_final<<<TOT, 256>>>(timew, vbn_g, vbn_b, mbn_g, mbn_b, out);
}

// round 6
// speedup vs baseline: 1.1342x; 1.1053x over previous
#include <cuda_runtime.h>
#include <math.h>
#include <stdint.h>

#define DINL __device__ __forceinline__

// ---------- packed fp32x2 helpers (sm_103a) ----------
DINL unsigned long long pack2(float x, float y){
    unsigned long long r;
    asm("mov.b64 %0, {%1,%2};" : "=l"(r) : "f"(x), "f"(y));
    return r;
}
DINL void unpack2(unsigned long long v, float& x, float& y){
    asm("mov.b64 {%0,%1}, %2;" : "=f"(x), "=f"(y) : "l"(v));
}
DINL void fma2(unsigned long long& d, unsigned long long a, unsigned long long b){
    asm("fma.rn.f32x2 %0, %1, %2, %0;" : "+l"(d) : "l"(a), "l"(b));
}
DINL float sigm(float x){ return 1.0f / (1.0f + expf(-x)); }
DINL float tanh_fast(float x){
    float y;
    asm("tanh.approx.f32 %0, %1;" : "=f"(y) : "f"(x));
    return y;
}

// ---------- sizes ----------
#define B_   8
#define S_   32
#define P_   5
#define C_   528
#define H_   784
#define M_   128
#define NSP  196
#define TOT  1280
#define BSN  256
#define OUTW 1697

// ---------- device scratch ----------
__device__ __align__(16) float g_GI[BSN * 3 * H_];
__device__ __align__(16) float g_h[2][B_ * H_];
__device__ __align__(16) float g_pref[BSN * H_];
__device__ __align__(16) float g_patt[BSN * M_];
__device__ __align__(16) float g_mot[BSN * M_];
__device__ __align__(16) float g_Wt[C_ * M_];
__device__ __align__(16) float g_vidpre[(size_t)TOT * 784];
__device__ __align__(16) float g_bnPart[TOT * 8];
__device__ __align__(16) float g_mstats[2 * M_];
__device__ __align__(16) float g_vstats[8];

// ---------- prep: transpose Wv_w [128,528] -> g_Wt [528,128] ----------
__global__ void k_prep(const float* __restrict__ Wv_w){
    int i = blockIdx.x * 256 + threadIdx.x;
    if (i < C_ * M_){
        int m = i / C_, c = i % C_;
        g_Wt[c * M_ + m] = Wv_w[i];
    }
}

// ---------- generic NT GEMM: C[i,j] = sum_k A[i,k]*B[j,k] (+bias[j]) ----------
__global__ void k_gemm_nt(const float* __restrict__ Aext, const float* __restrict__ Bm,
                          const float* __restrict__ bias, int atag, int ctag,
                          int M, int N, int K){
    const float* A = (atag == 0) ? Aext : g_pref;
    float* C = (ctag == 0) ? g_GI : (ctag == 1 ? g_patt : g_mot);
    __shared__ float As[32][33];
    __shared__ float Bs[64][33];
    int i0 = blockIdx.y * 32, j0 = blockIdx.x * 64;
    int tid = threadIdx.x;
    int ti = tid >> 4, tj = tid & 15;
    float acc[2][4] = {{0,0,0,0},{0,0,0,0}};
    for (int k0 = 0; k0 < K; k0 += 32){
        #pragma unroll
        for (int r = 0; r < 4; r++){
            int idx = tid + r * 256, row = idx >> 5, col = idx & 31;
            float v = 0.0f;
            if (i0 + row < M && k0 + col < K) v = A[(size_t)(i0 + row) * K + k0 + col];
            As[row][col] = v;
        }
        #pragma unroll
        for (int r = 0; r < 8; r++){
            int idx = tid + r * 256, row = idx >> 5, col = idx & 31;
            float v = 0.0f;
            if (j0 + row < N && k0 + col < K) v = Bm[(size_t)(j0 + row) * K + k0 + col];
            Bs[row][col] = v;
        }
        __syncthreads();
        #pragma unroll
        for (int kk = 0; kk < 32; kk++){
            float a0 = As[ti*2][kk], a1 = As[ti*2+1][kk];
            float b0 = Bs[tj*4][kk], b1 = Bs[tj*4+1][kk];
            float b2 = Bs[tj*4+2][kk], b3 = Bs[tj*4+3][kk];
            acc[0][0] += a0*b0; acc[0][1] += a0*b1; acc[0][2] += a0*b2; acc[0][3] += a0*b3;
            acc[1][0] += a1*b0; acc[1][1] += a1*b1; acc[1][2] += a1*b2; acc[1][3] += a1*b3;
        }
        __syncthreads();
    }
    #pragma unroll
    for (int r = 0; r < 2; r++)
        #pragma unroll
        for (int c = 0; c < 4; c++){
            int i = i0 + ti*2 + r, j = j0 + tj*4 + c;
            if (i < M && j < N){
                float v = acc[r][c];
                if (bias) v += bias[j];
                C[(size_t)i * N + j] = v;
            }
        }
}

// ---------- GRU recurrent step (R3 structure + LDG.128 weight stream) ----------
// grid(196), block(384) = 12 warps. Warp wid -> (jj = wid/3, gate g = wid%3).
// Each warp: dot(Whh[g*H + j], h[b]) for all 8 batches, weights via 7 unrolled
// float4 loads (MLP ~7 LDG.128/warp), f32x2 accumulate. Gates recombined in smem.
#define GRU_THREADS 384
__global__ void __launch_bounds__(GRU_THREADS)
k_gru_step(const float* __restrict__ Whh, const float* __restrict__ bhh, int s){
    __shared__ __align__(16) float4 hs4[B_ * (H_ / 4)];   // 8*196 float4 = 25088 B
    __shared__ float gsum[4][3][B_];
    const float* hin = g_h[s & 1];
    float* hout = g_h[(s + 1) & 1];
    int tid = threadIdx.x, wid = tid >> 5, lane = tid & 31;

    if (s > 0){
        const float4* src = reinterpret_cast<const float4*>(hin);
        for (int i = tid; i < B_ * (H_ / 4); i += GRU_THREADS) hs4[i] = src[i];
    }
    __syncthreads();

    int jj = wid / 3, g = wid % 3;          // wid 0..11 -> jj 0..3, g 0..2
    int j = blockIdx.x * 4 + jj;

    float red[B_];
    #pragma unroll
    for (int b = 0; b < B_; b++) red[b] = 0.0f;

    if (s > 0){
        const float4* w = reinterpret_cast<const float4*>(Whh + (size_t)(g * H_ + j) * H_);
        unsigned long long acc[B_];
        #pragma unroll
        for (int b = 0; b < B_; b++) acc[b] = 0ULL;
        #pragma unroll
        for (int it = 0; it < 7; it++){
            int k4 = lane + it * 32;
            if (it < 6 || lane < 4){
                float4 wv = w[k4];
                unsigned long long wl = pack2(wv.x, wv.y), wh = pack2(wv.z, wv.w);
                #pragma unroll
                for (int b = 0; b < B_; b++){
                    float4 h4 = hs4[b * (H_ / 4) + k4];
                    fma2(acc[b], wl, pack2(h4.x, h4.y));
                    fma2(acc[b], wh, pack2(h4.z, h4.w));
                }
            }
        }
        #pragma unroll
        for (int b = 0; b < B_; b++){
            float x, y; unpack2(acc[b], x, y);
            red[b] = x + y;
        }
        #pragma unroll
        for (int o = 16; o; o >>= 1)
            #pragma unroll
            for (int b = 0; b < B_; b++)
                red[b] += __shfl_down_sync(0xffffffffu, red[b], o);
    }
    if (lane == 0){
        #pragma unroll
        for (int b = 0; b < B_; b++) gsum[jj][g][b] = red[b];
    }
    __syncthreads();

    if (tid < 32){
        int jj2 = tid >> 3, b = tid & 7;
        int j2 = blockIdx.x * 4 + jj2;
        int bs = b * S_ + s;
        const float* gi = g_GI + (size_t)bs * (3 * H_);
        const float* hsf = reinterpret_cast<const float*>(hs4);
        float r = sigm(gi[j2] + gsum[jj2][0][b] + bhh[j2]);
        float z = sigm(gi[H_ + j2] + gsum[jj2][1][b] + bhh[H_ + j2]);
        float n = tanhf(gi[2 * H_ + j2] + r * (gsum[jj2][2][b] + bhh[2 * H_ + j2]));
        float hold = (s > 0) ? hsf[b * H_ + j2] : 0.0f;
        float hn = (1.0f - z) * n + z * hold;
        hout[b * H_ + j2] = hn;
        g_pref[(size_t)bs * H_ + j2] = hn;
    }
}

// ---------- fused attention + softmax + 1x1 conv; one CTA per t ----------
#define ATT_THREADS 448
#define NCC 8
__global__ void __launch_bounds__(ATT_THREADS, 1)
k_att(const float* __restrict__ video, const float* __restrict__ Wv_b,
      const float* __restrict__ Wpv, const float* __restrict__ conv_w,
      const float* __restrict__ conv_b){
    __shared__ float Vs[2][NCC * NSP];
    __shared__ __align__(16) float Ws[2][NCC * M_];
    __shared__ float sc[NSP];
    __shared__ float attb[NSP];
    __shared__ float cw[4 * C_];
    __shared__ float wS[14][8];

    int t = blockIdx.x;
    const float* V = video + (size_t)t * (C_ * NSP);
    int tid = threadIdx.x;
    int tj = tid & 15, ti = tid >> 4;
    int m0 = tj * 8, n0 = ti * 7;

    for (int i = tid; i < 4 * C_; i += ATT_THREADS) cw[i] = conv_w[i];

    int wst[3];
    #pragma unroll
    for (int r = 0; r < 3; r++){
        int idx = tid + r * ATT_THREADS;
        if (idx < NCC * M_){
            int cc = idx >> 7, m = idx & 127;
            int p = m >> 1;
            int q = ((p & 3) << 4) | (p >> 2);
            wst[r] = cc * M_ + q * 2 + (m & 1);
        } else wst[r] = -1;
    }

    #pragma unroll
    for (int r = 0; r < 4; r++){
        int idx = tid + r * ATT_THREADS;
        if (idx < NCC * NSP) Vs[0][idx] = V[idx];
    }
    #pragma unroll
    for (int r = 0; r < 3; r++)
        if (wst[r] >= 0) Ws[0][wst[r]] = g_Wt[tid + r * ATT_THREADS];
    __syncthreads();

    unsigned long long acc[7][4];
    #pragma unroll
    for (int i = 0; i < 7; i++)
        #pragma unroll
        for (int j = 0; j < 4; j++) acc[i][j] = 0ULL;

    const int NSTAGE = C_ / NCC; // 66
    for (int st = 0; st < NSTAGE; st++){
        int cur = st & 1;
        float vtmp[4], wtmp[3];
        bool has = (st + 1 < NSTAGE);
        if (has){
            const float* Vn = V + (st + 1) * (NCC * NSP);
            const float* Wn = g_Wt + (st + 1) * (NCC * M_);
            #pragma unroll
            for (int r = 0; r < 4; r++){
                int idx = tid + r * ATT_THREADS;
                vtmp[r] = (idx < NCC * NSP) ? Vn[idx] : 0.0f;
            }
            #pragma unroll
            for (int r = 0; r < 3; r++)
                wtmp[r] = (wst[r] >= 0) ? Wn[tid + r * ATT_THREADS] : 0.0f;
        }
        const float* vsc = Vs[cur];
        const unsigned long long* wsc = reinterpret_cast<const unsigned long long*>(Ws[cur]);
        #pragma unroll
        for (int cc = 0; cc < NCC; cc++){
            unsigned long long bv[4];
            #pragma unroll
            for (int j = 0; j < 4; j++) bv[j] = wsc[cc * 64 + j * 16 + tj];
            #pragma unroll
            for (int i = 0; i < 7; i++){
                float a = vsc[cc * NSP + n0 + i];
                unsigned long long av = pack2(a, a);
                #pragma unroll
                for (int j = 0; j < 4; j++) fma2(acc[i][j], av, bv[j]);
            }
        }
        if (has){
            float* vd = Vs[cur ^ 1];
            float* wd = Ws[cur ^ 1];
            #pragma unroll
            for (int r = 0; r < 4; r++){
                int idx = tid + r * ATT_THREADS;
                if (idx < NCC * NSP) vd[idx] = vtmp[r];
            }
            #pragma unroll
            for (int r = 0; r < 3; r++)
                if (wst[r] >= 0) wd[wst[r]] = wtmp[r];
        }
        __syncthreads();
    }

    int bs = t / P_;
    const float* pa = g_patt + (size_t)bs * M_;
    float sp[7] = {0,0,0,0,0,0,0};
    #pragma unroll
    for (int j = 0; j < 4; j++){
        int m = m0 + 2 * j;
        float2 pv = *reinterpret_cast<const float2*>(pa + m);
        float2 bb = *reinterpret_cast<const float2*>(Wv_b + m);
        float2 ww = *reinterpret_cast<const float2*>(Wpv + m);
        #pragma unroll
        for (int i = 0; i < 7; i++){
            float x, y; unpack2(acc[i][j], x, y);
            x = tanh_fast(x + pv.x + bb.x);
            y = tanh_fast(y + pv.y + bb.y);
            sp[i] += x * ww.x + y * ww.y;
        }
    }
    #pragma unroll
    for (int o = 8; o >= 1; o >>= 1)
        #pragma unroll
        for (int i = 0; i < 7; i++)
            sp[i] += __shfl_xor_sync(0xffffffffu, sp[i], o);
    if (tj == 0){
        #pragma unroll
        for (int i = 0; i < 7; i++) sc[n0 + i] = sp[i];
    }
    __syncthreads();

    if (tid < 32){
        float mx = -3.4e38f;
        for (int n = tid; n < NSP; n += 32) mx = fmaxf(mx, sc[n]);
        #pragma unroll
        for (int o = 16; o; o >>= 1) mx = fmaxf(mx, __shfl_xor_sync(0xffffffffu, mx, o));
        float sm = 0.0f;
        for (int n = tid; n < NSP; n += 32){ float e = expf(sc[n] - mx); attb[n] = e; sm += e; }
        #pragma unroll
        for (int o = 16; o; o >>= 1) sm += __shfl_xor_sync(0xffffffffu, sm, o);
        float inv = 1.0f / sm;
        for (int n = tid; n < NSP; n += 32) attb[n] *= inv;
    }
    __syncthreads();

    float d0 = 0.f, d1 = 0.f, d2 = 0.f, d3 = 0.f;
    int n = tid >> 1, half = tid & 1;
    if (tid < 392){
        const float4* fp = reinterpret_cast<const float4*>(V + (size_t)n * C_ + half * 264);
        #pragma unroll 4
        for (int q = 0; q < 66; q++){
            float4 v4 = fp[q];
            int c = half * 264 + q * 4;
            d0 += v4.x*cw[c]       + v4.y*cw[c+1]       + v4.z*cw[c+2]       + v4.w*cw[c+3];
            d1 += v4.x*cw[528+c]   + v4.y*cw[528+c+1]   + v4.z*cw[528+c+2]   + v4.w*cw[528+c+3];
            d2 += v4.x*cw[1056+c]  + v4.y*cw[1056+c+1]  + v4.z*cw[1056+c+2]  + v4.w*cw[1056+c+3];
            d3 += v4.x*cw[1584+c]  + v4.y*cw[1584+c+1]  + v4.z*cw[1584+c+2]  + v4.w*cw[1584+c+3];
        }
    }
    d0 += __shfl_xor_sync(0xffffffffu, d0, 1);
    d1 += __shfl_xor_sync(0xffffffffu, d1, 1);
    d2 += __shfl_xor_sync(0xffffffffu, d2, 1);
    d3 += __shfl_xor_sync(0xffffffffu, d3, 1);

    float dsum[4] = {0,0,0,0}, dsq[4] = {0,0,0,0};
    if (tid < 392 && half == 0){
        float an = attb[n];
        float vv[4];
        vv[0] = an * d0 + conv_b[0];
        vv[1] = an * d1 + conv_b[1];
        vv[2] = an * d2 + conv_b[2];
        vv[3] = an * d3 + conv_b[3];
        #pragma unroll
        for (int o = 0; o < 4; o++){
            g_vidpre[(size_t)t * 784 + o * NSP + n] = vv[o];
            dsum[o] = vv[o];
            dsq[o] = vv[o] * vv[o];
        }
    }
    #pragma unroll
    for (int o = 0; o < 4; o++){
        #pragma unroll
        for (int sh = 16; sh; sh >>= 1){
            dsum[o] += __shfl_down_sync(0xffffffffu, dsum[o], sh);
            dsq[o]  += __shfl_down_sync(0xffffffffu, dsq[o], sh);
        }
    }
    int wid = tid >> 5, lane = tid & 31;
    if (lane == 0){
        #pragma unroll
        for (int o = 0; o < 4; o++){ wS[wid][o] = dsum[o]; wS[wid][4 + o] = dsq[o]; }
    }
    __syncthreads();
    if (tid < 8){
        float a = 0.f;
        #pragma unroll
        for (int w = 0; w < 14; w++) a += wS[w][tid];
        g_bnPart[t * 8 + tid] = a;
    }
}

// ---------- motion BN stats over 256 rows ----------
__global__ void k_mstats(){
    int m = threadIdx.x;
    float sum = 0.f, sq = 0.f;
    for (int r = 0; r < BSN; r++){
        float v = g_mot[r * M_ + m];
        sum += v; sq += v * v;
    }
    float mu = sum / (float)BSN;
    float var = sq / (float)BSN - mu * mu;
    g_mstats[m] = mu;
    g_mstats[M_ + m] = rsqrtf(var + 1e-5f);
}

// ---------- video BN stats reduce ----------
__global__ void k_vstats(){
    __shared__ float red[256];
    __shared__ float tot[8];
    int tid = threadIdx.x;
    float part[8] = {0,0,0,0,0,0,0,0};
    for (int t = tid; t < TOT; t += 256)
        #pragma unroll
        for (int k = 0; k < 8; k++) part[k] += g_bnPart[t * 8 + k];
    for (int k = 0; k < 8; k++){
        red[tid] = part[k];
        __syncthreads();
        for (int o = 128; o; o >>= 1){
            if (tid < o) red[tid] += red[tid + o];
            __syncthreads();
        }
        if (tid == 0) tot[k] = red[0];
        __syncthreads();
    }
    if (tid < 4){
        float cnt = (float)TOT * (float)NSP;
        float mu = tot[tid] / cnt;
        float var = tot[4 + tid] / cnt - mu * mu;
        g_vstats[tid] = mu;
        g_vstats[4 + tid] = rsqrtf(var + 1e-5f);
    }
}

// ---------- final assembly ----------
__global__ void k_final(const float* __restrict__ tw,
                        const float* __restrict__ vbn_g, const float* __restrict__ vbn_b,
                        const float* __restrict__ mbn_g, const float* __restrict__ mbn_b,
                        float* __restrict__ out){
    int t = blockIdx.x, bs = t / P_, p = t % P_;
    float* o = out + (size_t)t * OUTW;
    for (int c = threadIdx.x; c < OUTW; c += 256){
        float v;
        if (c == 0) v = tw[p];
        else if (c < 785) v = g_pref[(size_t)bs * H_ + (c - 1)];
        else if (c < 913){
            int m = c - 785;
            float x = g_mot[bs * M_ + m];
            v = fmaxf((x - g_mstats[m]) * g_mstats[M_ + m] * mbn_g[m] + mbn_b[m], 0.f);
        } else {
            int idx = c - 913, ch = idx / NSP;
            float x = g_vidpre[(size_t)t * 784 + idx];
            v = fmaxf((x - g_vstats[ch]) * g_vstats[4 + ch] * vbn_g[ch] + vbn_b[ch], 0.f);
        }
        o[c] = v;
    }
}

// ---------- launcher ----------
extern "C" void kernel_launch(void* const* d_in, const int* in_sizes, int n_in,
                              void* d_out, int out_size){
    const float* fov      = (const float*)d_in[0];
    const float* motion   = (const float*)d_in[1];
    const float* video    = (const float*)d_in[2];
    const float* timew    = (const float*)d_in[3];
    const float* gru_w_ih = (const float*)d_in[4];
    const float* gru_w_hh = (const float*)d_in[5];
    const float* gru_b_ih = (const float*)d_in[6];
    const float* gru_b_hh = (const float*)d_in[7];
    const float* Wp       = (const float*)d_in[8];
    const float* Wv_w     = (const float*)d_in[9];
    const float* Wv_b     = (const float*)d_in[10];
    const float* Wpv_w    = (const float*)d_in[11];
    const float* conv_w   = (const float*)d_in[13];
    const float* conv_b   = (const float*)d_in[14];
    const float* vbn_g    = (const float*)d_in[15];
    const float* vbn_b    = (const float*)d_in[16];
    const float* me_w     = (const float*)d_in[17];
    const float* me_b     = (const float*)d_in[18];
    const float* mbn_g    = (const float*)d_in[19];
    const float* mbn_b    = (const float*)d_in[20];
    float* out = (float*)d_out;

    k_prep<<<264, 256>>>(Wv_w);
    k_gemm_nt<<<dim3(37, 8), 256>>>(fov, gru_w_ih, gru_b_ih, 0, 0, BSN, 3 * H_, C_);
    for (int s = 0; s < S_; s++)
        k_gru_step<<<196, GRU_THREADS>>>(gru_w_hh, gru_b_hh, s);
    k_gemm_nt<<<dim3(2, 8), 256>>>(nullptr, Wp, nullptr, 1, 1, BSN, M_, H_);
    k_gemm_nt<<<dim3(2, 8), 256>>>(motion, me_w, me_b, 0, 2, BSN, M_, 90);
    k_att<<<TOT, ATT_THREADS>>>(video, Wv_b, Wpv_w, conv_w, conv_b);
    k_mstats<<<1, 128>>>();
    k_vstats<<<1, 256>>>();
    k_final<<<TOT, 256>>>(timew, vbn_g, vbn_b, mbn_g, mbn_b, out);
}